// round 2
// baseline (speedup 1.0000x reference)
#include <cuda_runtime.h>
#include <cuda_bf16.h>
#include <math.h>

// ---------------------------------------------------------------------------
// Tree constants (structure is deterministic given depth; adjacency inputs are
// redundant: reversed-heap layout => levels are contiguous blocks, children of
// level-L parent m are prev-level rows 2m and 2m+1).
// ---------------------------------------------------------------------------
#define NC 131071            // cube nodes, depth 17
#define NA 4095              // lit_a nodes, depth 12
#define NB 4095              // lit_b nodes, depth 12
#define TOTAL_NODES (NC + NA + NB)   // 139261
#define HDIM 128

// Persistent state for all nodes of all three trees (float, 71MB each).
__device__ float g_h[(size_t)TOTAL_NODES * HDIM];
__device__ float g_c[(size_t)TOTAL_NODES * HDIM];

struct Seg {
    const int* feats;   // already offset to this level's first parent
    int gp0;            // global node row of first parent at this level
    int gq0;            // global node row of first child (prev level block)
    int M;              // number of parents at this level
    int ctaEnd;         // cumulative CTA end (dispatch)
};

#define TM 32   // parents per CTA

__device__ __forceinline__ float sigf(float x) { return 1.0f / (1.0f + expf(-x)); }

#define FMA4(acc, s, b) do { \
    (acc).x = fmaf((s), (b).x, (acc).x); \
    (acc).y = fmaf((s), (b).y, (acc).y); \
    (acc).z = fmaf((s), (b).z, (acc).z); \
    (acc).w = fmaf((s), (b).w, (acc).w); } while (0)

// ---------------------------------------------------------------------------
// Fused level kernel.
// LEAF=true:  iou = X@W_iou ; c = i*u ; h = o*tanh(c)
// LEAF=false: iou = X@W_iou + (h0+h1)@U_iou ; xf = X@W_f ; huK = hK@U_f
//             f_k = sig(xf + b_f + huK); c = i*u + f0*c0 + f1*c1; h = o*tanh(c)
// 256 threads, TM=32 parents/CTA, thread tile 4(m) x 4(n), K=128.
// ---------------------------------------------------------------------------
template <bool LEAF>
__global__ void __launch_bounds__(256)
level_kernel(Seg s0, Seg s1, Seg s2,
             const float* __restrict__ emb,
             const float* __restrict__ Wiou, const float* __restrict__ Uiou,
             const float* __restrict__ Wf,   const float* __restrict__ Uf,
             const float* __restrict__ biou, const float* __restrict__ bf)
{
    extern __shared__ float sm[];
    float* Xs = sm;                 // [32][128]
    float* Hp = sm + TM * HDIM;     // [64][128] (internal only)

    // dispatch: which tree segment does this CTA belong to
    int cta = blockIdx.x;
    Seg s;
    int rel;
    if (cta < s0.ctaEnd)       { s = s0; rel = cta; }
    else if (cta < s1.ctaEnd)  { s = s1; rel = cta - s0.ctaEnd; }
    else                       { s = s2; rel = cta - s1.ctaEnd; }

    const int m0   = rel * TM;
    int Mrem = s.M - m0; if (Mrem > TM) Mrem = TM;

    const int tid = threadIdx.x;

    // ---- load A tiles into smem ----
    // Xs: embedding rows of the 32 parents (float4-coalesced)
    const float4* emb4 = (const float4*)emb;
    for (int i = tid; i < TM * 32; i += 256) {
        int m = i >> 5, q = i & 31;
        float4 v = make_float4(0.f, 0.f, 0.f, 0.f);
        if (m < Mrem) {
            int f = __ldg(&s.feats[m0 + m]);
            v = emb4[(size_t)f * 32 + q];
        }
        ((float4*)Xs)[i] = v;
    }
    if (!LEAF) {
        const float4* gh4 = (const float4*)g_h;
        for (int i = tid; i < 2 * TM * 32; i += 256) {
            int r = i >> 5, q = i & 31;
            float4 v = make_float4(0.f, 0.f, 0.f, 0.f);
            if (r < 2 * Mrem)
                v = gh4[(size_t)(s.gq0 + 2 * m0 + r) * 32 + q];
            ((float4*)Hp)[i] = v;
        }
    }
    __syncthreads();

    const int ng = tid & 31;       // n-group: cols n0..n0+3
    const int mg = tid >> 5;       // m-group: rows mb..mb+3
    const int mb = mg * 4;

    float4 aI[4], aO[4], aU[4], aXF[4], aH0[4], aH1[4];
    #pragma unroll
    for (int mm = 0; mm < 4; mm++) {
        aI[mm] = make_float4(0.f,0.f,0.f,0.f);
        aO[mm] = make_float4(0.f,0.f,0.f,0.f);
        aU[mm] = make_float4(0.f,0.f,0.f,0.f);
        aXF[mm] = make_float4(0.f,0.f,0.f,0.f);
        aH0[mm] = make_float4(0.f,0.f,0.f,0.f);
        aH1[mm] = make_float4(0.f,0.f,0.f,0.f);
    }

    const float4* W4  = (const float4*)Wiou;   // row k: 96 float4
    const float4* U4  = (const float4*)Uiou;
    const float4* Wf4 = (const float4*)Wf;     // row k: 32 float4
    const float4* Uf4 = (const float4*)Uf;

    for (int k = 0; k < HDIM; k++) {
        const int r96 = k * 96 + ng;
        float4 wi = __ldg(&W4[r96]);
        float4 wo = __ldg(&W4[r96 + 32]);
        float4 wu = __ldg(&W4[r96 + 64]);
        float4 ui, uo, uu, wf, uf;
        if (!LEAF) {
            ui = __ldg(&U4[r96]);
            uo = __ldg(&U4[r96 + 32]);
            uu = __ldg(&U4[r96 + 64]);
            wf = __ldg(&Wf4[k * 32 + ng]);
            uf = __ldg(&Uf4[k * 32 + ng]);
        }
        #pragma unroll
        for (int mm = 0; mm < 4; mm++) {
            float x = Xs[(mb + mm) * HDIM + k];
            if (LEAF) {
                FMA4(aI[mm], x, wi);
                FMA4(aO[mm], x, wo);
                FMA4(aU[mm], x, wu);
            } else {
                float h0 = Hp[(2 * (mb + mm)) * HDIM + k];
                float h1 = Hp[(2 * (mb + mm) + 1) * HDIM + k];
                float hs = h0 + h1;
                FMA4(aI[mm], x, wi);  FMA4(aI[mm], hs, ui);
                FMA4(aO[mm], x, wo);  FMA4(aO[mm], hs, uo);
                FMA4(aU[mm], x, wu);  FMA4(aU[mm], hs, uu);
                FMA4(aXF[mm], x, wf);
                FMA4(aH0[mm], h0, uf);
                FMA4(aH1[mm], h1, uf);
            }
        }
    }

    // ---- epilogue: gates + state update ----
    const float4* b4 = (const float4*)biou;
    float4 biF = __ldg(&b4[ng]);
    float4 boF = __ldg(&b4[32 + ng]);
    float4 buF = __ldg(&b4[64 + ng]);
    float4 bfF = make_float4(0.f,0.f,0.f,0.f);
    if (!LEAF) bfF = __ldg(&((const float4*)bf)[ng]);

    const float* pbi = (const float*)&biF;
    const float* pbo = (const float*)&boF;
    const float* pbu = (const float*)&buF;
    const float* pbf = (const float*)&bfF;

    #pragma unroll
    for (int mm = 0; mm < 4; mm++) {
        int mi = mb + mm;
        if (mi >= Mrem) continue;
        int gp = s.gp0 + m0 + mi;

        float4 c0v = make_float4(0.f,0.f,0.f,0.f), c1v = c0v;
        if (!LEAF) {
            size_t cb = (size_t)(s.gq0 + 2 * (m0 + mi)) * 32 + ng;
            c0v = ((const float4*)g_c)[cb];
            c1v = ((const float4*)g_c)[cb + 32];
        }
        const float* pI  = (const float*)&aI[mm];
        const float* pO  = (const float*)&aO[mm];
        const float* pU  = (const float*)&aU[mm];
        const float* pXF = (const float*)&aXF[mm];
        const float* pH0 = (const float*)&aH0[mm];
        const float* pH1 = (const float*)&aH1[mm];
        const float* pc0 = (const float*)&c0v;
        const float* pc1 = (const float*)&c1v;

        float4 cn, hn;
        float* pcn = (float*)&cn;
        float* phn = (float*)&hn;
        #pragma unroll
        for (int nn = 0; nn < 4; nn++) {
            float iv = sigf(pI[nn] + pbi[nn]);
            float ov = sigf(pO[nn] + pbo[nn]);
            float uv = tanhf(pU[nn] + pbu[nn]);
            float cv;
            if (LEAF) {
                cv = iv * uv;
            } else {
                float xfv = pXF[nn] + pbf[nn];
                float f0 = sigf(xfv + pH0[nn]);
                float f1 = sigf(xfv + pH1[nn]);
                cv = iv * uv + f0 * pc0[nn] + f1 * pc1[nn];
            }
            pcn[nn] = cv;
            phn[nn] = ov * tanhf(cv);
        }
        ((float4*)g_c)[(size_t)gp * 32 + ng] = cn;
        ((float4*)g_h)[(size_t)gp * 32 + ng] = hn;
    }
}

// ---------------------------------------------------------------------------
// Fusion head: h = h_a * (h_b . h_c); relu(relu(h@fc1 + b1)@fc2 + b2) -> 3
// ---------------------------------------------------------------------------
__global__ void final_kernel(const float* __restrict__ fc1w,
                             const float* __restrict__ fc1b,
                             const float* __restrict__ fc2w,
                             const float* __restrict__ fc2b,
                             float* __restrict__ out)
{
    __shared__ float red[128];
    __shared__ float hv[128];
    __shared__ float y1[64];
    int t = threadIdx.x;  // 128 threads

    const float* hC = g_h + (size_t)(NC - 1) * HDIM;                 // cube root
    const float* hA = g_h + (size_t)(NC + NA - 1) * HDIM;            // lit_a root
    const float* hB = g_h + (size_t)(NC + NA + NB - 1) * HDIM;       // lit_b root

    red[t] = hB[t] * hC[t];
    __syncthreads();
    for (int ss = 64; ss > 0; ss >>= 1) {
        if (t < ss) red[t] += red[t + ss];
        __syncthreads();
    }
    float ssum = red[0];
    hv[t] = hA[t] * ssum;
    __syncthreads();

    if (t < 64) {
        float a = fc1b[t];
        #pragma unroll 4
        for (int i = 0; i < 128; i++) a = fmaf(hv[i], fc1w[i * 64 + t], a);
        y1[t] = fmaxf(a, 0.f);
    }
    __syncthreads();
    if (t < 3) {
        float a = fc2b[t];
        #pragma unroll
        for (int i = 0; i < 64; i++) a = fmaf(y1[i], fc2w[i * 3 + t], a);
        out[t] = fmaxf(a, 0.f);
    }
}

// ---------------------------------------------------------------------------
// Host side
// ---------------------------------------------------------------------------
static inline Seg make_seg(const int* feats, int base, int D, int it)
{
    int N = (1 << D) - 1;
    int d = D - 1 - it;
    Seg s;
    s.M    = 1 << d;
    int pLoc = N - (1 << (d + 1)) + 1;
    int qLoc = (it >= 1) ? (N - (1 << (d + 2)) + 1) : 0;
    s.feats = feats + pLoc;
    s.gp0   = base + pLoc;
    s.gq0   = base + qLoc;
    s.ctaEnd = 0;
    return s;
}

static inline Seg empty_seg()
{
    Seg s; s.feats = nullptr; s.gp0 = 0; s.gq0 = 0; s.M = 0; s.ctaEnd = 0;
    return s;
}

extern "C" void kernel_launch(void* const* d_in, const int* in_sizes, int n_in,
                              void* d_out, int out_size)
{
    const int*   cf    = (const int*)  d_in[0];
    const int*   af    = (const int*)  d_in[4];
    const int*   bfeat = (const int*)  d_in[8];
    const float* emb   = (const float*)d_in[12];
    const float* W_iou = (const float*)d_in[13];
    const float* b_iou = (const float*)d_in[14];
    const float* U_iou = (const float*)d_in[15];
    const float* W_f   = (const float*)d_in[16];
    const float* b_f   = (const float*)d_in[17];
    const float* U_f   = (const float*)d_in[18];
    const float* fc1w  = (const float*)d_in[19];
    const float* fc1b  = (const float*)d_in[20];
    const float* fc2w  = (const float*)d_in[21];
    const float* fc2b  = (const float*)d_in[22];

    const int baseC = 0, baseA = NC, baseB = NC + NA;

    for (int it = 0; it < 17; it++) {
        Seg s0 = make_seg(cf, baseC, 17, it);
        Seg s1 = (it <= 11) ? make_seg(af, baseA, 12, it) : empty_seg();
        Seg s2 = (it <= 11) ? make_seg(bfeat, baseB, 12, it) : empty_seg();

        int e0 = (s0.M + TM - 1) / TM;
        int e1 = e0 + (s1.M + TM - 1) / TM;
        int e2 = e1 + (s2.M + TM - 1) / TM;
        s0.ctaEnd = e0; s1.ctaEnd = e1; s2.ctaEnd = e2;

        if (it == 0) {
            size_t shmem = (size_t)TM * HDIM * sizeof(float);            // 16KB
            level_kernel<true><<<e2, 256, shmem>>>(s0, s1, s2, emb,
                W_iou, U_iou, W_f, U_f, b_iou, b_f);
        } else {
            size_t shmem = (size_t)(TM + 2 * TM) * HDIM * sizeof(float); // 48KB
            level_kernel<false><<<e2, 256, shmem>>>(s0, s1, s2, emb,
                W_iou, U_iou, W_f, U_f, b_iou, b_f);
        }
    }

    final_kernel<<<1, 128>>>(fc1w, fc1b, fc2w, fc2b, (float*)d_out);
}

// round 4
// speedup vs baseline: 1.5379x; 1.5379x over previous
#include <cuda_runtime.h>
#include <cuda_bf16.h>
#include <math.h>

// ---------------------------------------------------------------------------
// Tree constants. Reversed-heap layout => levels are contiguous blocks,
// children of level-L parent m are prev-level rows 2m, 2m+1 (verified R1).
// ---------------------------------------------------------------------------
#define NC 131071            // cube nodes, depth 17
#define NA 4095              // lit_a nodes, depth 12
#define NB 4095              // lit_b nodes, depth 12
#define TOTAL_NODES (NC + NA + NB)   // 139261
#define HDIM 128
#define VOCAB 50000

// Persistent state + precomputed input-transform table.
__device__ float g_h[(size_t)TOTAL_NODES * HDIM];
__device__ float g_c[(size_t)TOTAL_NODES * HDIM];
// T[v][0:128)=i_pre, [128:256)=o_pre, [256:384)=u_pre, [384:512)=xf_pre (biases folded in)
__device__ float g_T[(size_t)VOCAB * 512];

struct Seg {
    const int* feats;
    int gp0;            // global row of first parent at this level
    int gq0;            // global row of first child (prev level block)
    int M;              // parents at this level
    int ctaEnd;
};

#define TM 32   // parents per CTA in level kernel

__device__ __forceinline__ float sigf(float x) { return 1.0f / (1.0f + expf(-x)); }

#define FMA4(acc, s, b) do { \
    (acc).x = fmaf((s), (b).x, (acc).x); \
    (acc).y = fmaf((s), (b).y, (acc).y); \
    (acc).z = fmaf((s), (b).z, (acc).z); \
    (acc).w = fmaf((s), (b).w, (acc).w); } while (0)

#define FMA2(acc, s, b) do { \
    (acc).x = fmaf((s), (b).x, (acc).x); \
    (acc).y = fmaf((s), (b).y, (acc).y); } while (0)

// ---------------------------------------------------------------------------
// K0: vocab table GEMM.  T[v, 0:384) = emb[v]@W_iou + b_iou
//                        T[v, 384:512) = emb[v]@W_f + b_f
// Tile: 64(M) x 32(N), K=128 fully staged in smem (48KB exactly).
// grid = (ceil(V/64), 16). 256 thr, per-thread 4m x 2n.
// ---------------------------------------------------------------------------
__global__ void __launch_bounds__(256)
table_kernel(const float* __restrict__ emb,
             const float* __restrict__ Wiou, const float* __restrict__ biou,
             const float* __restrict__ Wf,   const float* __restrict__ bf)
{
    __shared__ float As[64 * 128];   // [m][k]  32KB
    __shared__ float Bs[128 * 32];   // [k][n]  16KB

    const int mBlk = blockIdx.x * 64;
    const int nBlk = blockIdx.y * 32;
    const bool isF = (nBlk >= 384);
    const float* B    = isF ? Wf : Wiou;
    const float* bias = isF ? bf : biou;
    const int ldb  = isF ? 128 : 384;
    const int nOff = isF ? (nBlk - 384) : nBlk;
    const int tid = threadIdx.x;

    // load A tile (zero-pad past VOCAB)
    for (int i = tid; i < 64 * 32; i += 256) {
        int m = i >> 5, k4 = i & 31;
        float4 v = make_float4(0.f, 0.f, 0.f, 0.f);
        if (mBlk + m < VOCAB)
            v = ((const float4*)emb)[(size_t)(mBlk + m) * 32 + k4];
        ((float4*)As)[i] = v;
    }
    // load B tile: 128 rows x 8 float4
    for (int i = tid; i < 128 * 8; i += 256) {
        int k = i >> 3, n4 = i & 7;
        ((float4*)Bs)[i] = *(const float4*)(B + (size_t)k * ldb + nOff + n4 * 4);
    }
    __syncthreads();

    const int my = (tid >> 4) * 4;        // 4 m rows (16 groups)
    const int nx = (tid & 15) * 2;        // 2 n cols (16 groups)
    float2 acc0 = make_float2(0,0), acc1 = acc0, acc2 = acc0, acc3 = acc0;

    #pragma unroll 8
    for (int k = 0; k < 128; k++) {
        float2 b = *(const float2*)&Bs[k * 32 + nx];
        FMA2(acc0, As[(my + 0) * 128 + k], b);
        FMA2(acc1, As[(my + 1) * 128 + k], b);
        FMA2(acc2, As[(my + 2) * 128 + k], b);
        FMA2(acc3, As[(my + 3) * 128 + k], b);
    }

    float2 bv = *(const float2*)(bias + nOff + nx);
    acc0.x += bv.x; acc0.y += bv.y;
    acc1.x += bv.x; acc1.y += bv.y;
    acc2.x += bv.x; acc2.y += bv.y;
    acc3.x += bv.x; acc3.y += bv.y;

    float2* T2 = (float2*)g_T;
    const size_t colBase = (size_t)(nBlk + nx) >> 1;   // float2 col index
    if (mBlk + my + 0 < VOCAB) T2[((size_t)(mBlk + my + 0)) * 256 + colBase] = acc0;
    if (mBlk + my + 1 < VOCAB) T2[((size_t)(mBlk + my + 1)) * 256 + colBase] = acc1;
    if (mBlk + my + 2 < VOCAB) T2[((size_t)(mBlk + my + 2)) * 256 + colBase] = acc2;
    if (mBlk + my + 3 < VOCAB) T2[((size_t)(mBlk + my + 3)) * 256 + colBase] = acc3;
}

// ---------------------------------------------------------------------------
// Leaf kernel: pure elementwise from T.  c = sig(i)*tanh(u); h = sig(o)*tanh(c)
// 2 nodes per 256-thread CTA; 69632 leaves total.
// ---------------------------------------------------------------------------
#define LEAVES_C 65536
#define LEAVES_AB 2048
__global__ void __launch_bounds__(256)
leaf_kernel(const int* __restrict__ cf, const int* __restrict__ af,
            const int* __restrict__ bfeat)
{
    int node = blockIdx.x * 2 + (threadIdx.x >> 7);
    int col = threadIdx.x & 127;
    int grow; const int* fp; int loc;
    if (node < LEAVES_C)                    { loc = node;                        grow = loc;           fp = cf; }
    else if (node < LEAVES_C + LEAVES_AB)   { loc = node - LEAVES_C;             grow = NC + loc;      fp = af; }
    else                                    { loc = node - LEAVES_C - LEAVES_AB; grow = NC + NA + loc; fp = bfeat; }
    int f = __ldg(&fp[loc]);
    const float* T = g_T + (size_t)f * 512;
    float iv = sigf(__ldg(&T[col]));
    float ov = sigf(__ldg(&T[128 + col]));
    float uv = tanhf(__ldg(&T[256 + col]));
    float c = iv * uv;
    float h = ov * tanhf(c);
    g_c[(size_t)grow * HDIM + col] = c;
    g_h[(size_t)grow * HDIM + col] = h;
}

// ---------------------------------------------------------------------------
// Internal level kernel (recurrent part only):
//   iou = T[f][0:384) + (h0+h1)@U_iou ; hu_k = h_k@U_f
//   f_k = sig(T[f][384+n] + hu_k); c = i*u + f0*c0 + f1*c1; h = o*tanh(c)
// 256 threads, 32 parents/CTA, thread tile 4m x 4n per 128-col block.
// ---------------------------------------------------------------------------
__global__ void __launch_bounds__(256)
level_kernel(Seg s0, Seg s1, Seg s2,
             const float* __restrict__ Uiou, const float* __restrict__ Uf)
{
    __shared__ float Hp[2 * TM * HDIM];   // children h, 32KB
    __shared__ float Hs[TM * HDIM];       // h0+h1,      16KB

    int cta = blockIdx.x;
    Seg s; int rel;
    if (cta < s0.ctaEnd)      { s = s0; rel = cta; }
    else if (cta < s1.ctaEnd) { s = s1; rel = cta - s0.ctaEnd; }
    else                      { s = s2; rel = cta - s1.ctaEnd; }

    const int m0 = rel * TM;
    int Mrem = s.M - m0; if (Mrem > TM) Mrem = TM;
    const int tid = threadIdx.x;

    // load children h
    {
        const float4* gh4 = (const float4*)g_h;
        for (int i = tid; i < 2 * TM * 32; i += 256) {
            int r = i >> 5, q = i & 31;
            float4 v = make_float4(0.f, 0.f, 0.f, 0.f);
            if (r < 2 * Mrem)
                v = gh4[(size_t)(s.gq0 + 2 * m0 + r) * 32 + q];
            ((float4*)Hp)[i] = v;
        }
    }
    __syncthreads();
    // Hs = h0 + h1
    for (int i = tid; i < TM * 32; i += 256) {
        int m = i >> 5, q = i & 31;
        float4 a = ((const float4*)Hp)[(2 * m) * 32 + q];
        float4 b = ((const float4*)Hp)[(2 * m + 1) * 32 + q];
        ((float4*)Hs)[i] = make_float4(a.x + b.x, a.y + b.y, a.z + b.z, a.w + b.w);
    }
    __syncthreads();

    const int ng = tid & 31;
    const int mb = (tid >> 5) * 4;

    float4 aI[4], aO[4], aU[4], aH0[4], aH1[4];
    #pragma unroll
    for (int mm = 0; mm < 4; mm++) {
        aI[mm] = make_float4(0,0,0,0); aO[mm] = aI[mm]; aU[mm] = aI[mm];
        aH0[mm] = aI[mm]; aH1[mm] = aI[mm];
    }

    const float4* U4  = (const float4*)Uiou;   // row k: 96 float4
    const float4* Uf4 = (const float4*)Uf;     // row k: 32 float4

    float4 ui = __ldg(&U4[ng]);
    float4 uo = __ldg(&U4[ng + 32]);
    float4 uu = __ldg(&U4[ng + 64]);
    float4 uf = __ldg(&Uf4[ng]);

    #pragma unroll 2
    for (int k = 0; k < 127; k++) {
        const int r = (k + 1) * 96 + ng;
        float4 nui = __ldg(&U4[r]);
        float4 nuo = __ldg(&U4[r + 32]);
        float4 nuu = __ldg(&U4[r + 64]);
        float4 nuf = __ldg(&Uf4[(k + 1) * 32 + ng]);
        #pragma unroll
        for (int mm = 0; mm < 4; mm++) {
            float hs = Hs[(mb + mm) * HDIM + k];
            float h0 = Hp[(2 * (mb + mm)) * HDIM + k];
            float h1 = Hp[(2 * (mb + mm) + 1) * HDIM + k];
            FMA4(aI[mm], hs, ui); FMA4(aO[mm], hs, uo); FMA4(aU[mm], hs, uu);
            FMA4(aH0[mm], h0, uf); FMA4(aH1[mm], h1, uf);
        }
        ui = nui; uo = nuo; uu = nuu; uf = nuf;
    }
    {   // k = 127
        const int k = 127;
        #pragma unroll
        for (int mm = 0; mm < 4; mm++) {
            float hs = Hs[(mb + mm) * HDIM + k];
            float h0 = Hp[(2 * (mb + mm)) * HDIM + k];
            float h1 = Hp[(2 * (mb + mm) + 1) * HDIM + k];
            FMA4(aI[mm], hs, ui); FMA4(aO[mm], hs, uo); FMA4(aU[mm], hs, uu);
            FMA4(aH0[mm], h0, uf); FMA4(aH1[mm], h1, uf);
        }
    }

    // ---- epilogue ----
    #pragma unroll
    for (int mm = 0; mm < 4; mm++) {
        int mi = mb + mm;
        if (mi >= Mrem) continue;
        int gp = s.gp0 + m0 + mi;
        int f = __ldg(&s.feats[m0 + mi]);

        const float4* T4 = (const float4*)(g_T + (size_t)f * 512);
        float4 ti  = __ldg(&T4[ng]);
        float4 to  = __ldg(&T4[32 + ng]);
        float4 tu  = __ldg(&T4[64 + ng]);
        float4 txf = __ldg(&T4[96 + ng]);

        size_t cb = (size_t)(s.gq0 + 2 * (m0 + mi)) * 32 + ng;
        float4 c0v = ((const float4*)g_c)[cb];
        float4 c1v = ((const float4*)g_c)[cb + 32];

        const float* pI  = (const float*)&aI[mm];
        const float* pO  = (const float*)&aO[mm];
        const float* pU  = (const float*)&aU[mm];
        const float* pH0 = (const float*)&aH0[mm];
        const float* pH1 = (const float*)&aH1[mm];
        const float* pti = (const float*)&ti;
        const float* pto = (const float*)&to;
        const float* ptu = (const float*)&tu;
        const float* pxf = (const float*)&txf;
        const float* pc0 = (const float*)&c0v;
        const float* pc1 = (const float*)&c1v;

        float4 cn, hn;
        float* pcn = (float*)&cn;
        float* phn = (float*)&hn;
        #pragma unroll
        for (int nn = 0; nn < 4; nn++) {
            float iv = sigf(pI[nn] + pti[nn]);
            float ov = sigf(pO[nn] + pto[nn]);
            float uv = tanhf(pU[nn] + ptu[nn]);
            float f0 = sigf(pxf[nn] + pH0[nn]);
            float f1 = sigf(pxf[nn] + pH1[nn]);
            float cv = iv * uv + f0 * pc0[nn] + f1 * pc1[nn];
            pcn[nn] = cv;
            phn[nn] = ov * tanhf(cv);
        }
        ((float4*)g_c)[(size_t)gp * 32 + ng] = cn;
        ((float4*)g_h)[(size_t)gp * 32 + ng] = hn;
    }
}

// ---------------------------------------------------------------------------
// Fusion head
// ---------------------------------------------------------------------------
__global__ void final_kernel(const float* __restrict__ fc1w,
                             const float* __restrict__ fc1b,
                             const float* __restrict__ fc2w,
                             const float* __restrict__ fc2b,
                             float* __restrict__ out)
{
    __shared__ float red[128];
    __shared__ float hv[128];
    __shared__ float y1[64];
    int t = threadIdx.x;  // 128 threads

    const float* hC = g_h + (size_t)(NC - 1) * HDIM;
    const float* hA = g_h + (size_t)(NC + NA - 1) * HDIM;
    const float* hB = g_h + (size_t)(NC + NA + NB - 1) * HDIM;

    red[t] = hB[t] * hC[t];
    __syncthreads();
    for (int ss = 64; ss > 0; ss >>= 1) {
        if (t < ss) red[t] += red[t + ss];
        __syncthreads();
    }
    float ssum = red[0];
    hv[t] = hA[t] * ssum;
    __syncthreads();

    if (t < 64) {
        float a = fc1b[t];
        #pragma unroll 4
        for (int i = 0; i < 128; i++) a = fmaf(hv[i], fc1w[i * 64 + t], a);
        y1[t] = fmaxf(a, 0.f);
    }
    __syncthreads();
    if (t < 3) {
        float a = fc2b[t];
        #pragma unroll
        for (int i = 0; i < 64; i++) a = fmaf(y1[i], fc2w[i * 3 + t], a);
        out[t] = fmaxf(a, 0.f);
    }
}

// ---------------------------------------------------------------------------
// Host side
// ---------------------------------------------------------------------------
static inline Seg make_seg(const int* feats, int base, int D, int it)
{
    int N = (1 << D) - 1;
    int d = D - 1 - it;
    Seg s;
    s.M    = 1 << d;
    int pLoc = N - (1 << (d + 1)) + 1;
    int qLoc = N - (1 << (d + 2)) + 1;
    s.feats = feats + pLoc;
    s.gp0   = base + pLoc;
    s.gq0   = base + qLoc;
    s.ctaEnd = 0;
    return s;
}

static inline Seg empty_seg()
{
    Seg s; s.feats = nullptr; s.gp0 = 0; s.gq0 = 0; s.M = 0; s.ctaEnd = 0;
    return s;
}

extern "C" void kernel_launch(void* const* d_in, const int* in_sizes, int n_in,
                              void* d_out, int out_size)
{
    const int*   cf    = (const int*)  d_in[0];
    const int*   af    = (const int*)  d_in[4];
    const int*   bfeat = (const int*)  d_in[8];
    const float* emb   = (const float*)d_in[12];
    const float* W_iou = (const float*)d_in[13];
    const float* b_iou = (const float*)d_in[14];
    const float* U_iou = (const float*)d_in[15];
    const float* W_f   = (const float*)d_in[16];
    const float* b_f   = (const float*)d_in[17];
    const float* U_f   = (const float*)d_in[18];
    const float* fc1w  = (const float*)d_in[19];
    const float* fc1b  = (const float*)d_in[20];
    const float* fc2w  = (const float*)d_in[21];
    const float* fc2b  = (const float*)d_in[22];

    const int baseC = 0, baseA = NC, baseB = NC + NA;

    // K0: vocab input-transform table
    {
        dim3 grid((VOCAB + 63) / 64, 16);
        table_kernel<<<grid, 256>>>(emb, W_iou, b_iou, W_f, b_f);
    }
    // Leaves (level 0 of all three trees)
    leaf_kernel<<<(LEAVES_C + 2 * LEAVES_AB) / 2, 256>>>(cf, af, bfeat);

    // Internal levels
    for (int it = 1; it < 17; it++) {
        Seg s0 = make_seg(cf, baseC, 17, it);
        Seg s1 = (it <= 11) ? make_seg(af, baseA, 12, it) : empty_seg();
        Seg s2 = (it <= 11) ? make_seg(bfeat, baseB, 12, it) : empty_seg();

        int e0 = (s0.M + TM - 1) / TM;
        int e1 = e0 + (s1.M > 0 ? (s1.M + TM - 1) / TM : 0);
        int e2 = e1 + (s2.M > 0 ? (s2.M + TM - 1) / TM : 0);
        s0.ctaEnd = e0; s1.ctaEnd = e1; s2.ctaEnd = e2;

        level_kernel<<<e2, 256>>>(s0, s1, s2, U_iou, U_f);
    }

    final_kernel<<<1, 128>>>(fc1w, fc1b, fc2w, fc2b, (float*)d_out);
}